// round 5
// baseline (speedup 1.0000x reference)
#include <cuda_runtime.h>
#include <math.h>
#include <stdint.h>

#define BB 16
#define C1 128
#define C2 256
#define KK 4
#define HH 80
#define WW 80
#define HW 6400
#define EPSF 1e-5f
#define NPXT 100   // 6400/64 px tiles in kernel A

// ---------------- packed fp32x2 helpers (kept for k_conv1) ----------------
__device__ __forceinline__ void ffma2(unsigned long long& d,
                                      unsigned long long a,
                                      unsigned long long b) {
    asm("fma.rn.f32x2 %0, %1, %2, %0;" : "+l"(d) : "l"(a), "l"(b));
}
__device__ __forceinline__ unsigned long long pack2(float lo, float hi) {
    unsigned long long r;
    asm("mov.b64 %0, {%1, %2};" : "=l"(r) : "f"(lo), "f"(hi));
    return r;
}
__device__ __forceinline__ void unpack2(float& lo, float& hi, unsigned long long v) {
    asm("mov.b64 {%0, %1}, %2;" : "=f"(lo), "=f"(hi) : "l"(v));
}
// tf32 round-to-nearest
__device__ __forceinline__ uint32_t tf32r(float f) {
    uint32_t r;
    asm("cvt.rna.tf32.f32 %0, %1;" : "=r"(r) : "f"(f));
    return r;
}

// ---------------- scratch (static device globals; no allocs) ----------------
__device__ float g_y[BB * C2 * HW];            // post conv1+BN+SiLU feature
__device__ float g_partsum[BB * C2 * NPXT];
__device__ float g_partsq [BB * C2 * NPXT];
__device__ float g_mu [BB * C2];
__device__ float g_inv[BB * C2];
__device__ float g_attn[BB * KK];
__device__ float g_aggw[BB * C2 * 9 * C2];     // [b][ic][tap][oc], tf32-rounded
__device__ float g_aggb[BB * C2];

// ============================================================================
// Kernel A: y = SiLU(BN(x @ W1)) + per-(b,c) partial sum / sumsq
// ============================================================================
__global__ void __launch_bounds__(256) k_conv1(
    const float* __restrict__ x, const float* __restrict__ w1,
    const float* __restrict__ bng, const float* __restrict__ bnb,
    const float* __restrict__ bnm, const float* __restrict__ bnv)
{
    __shared__ __align__(16) float xs[8][64];
    __shared__ __align__(16) float ws[8][64];
    __shared__ float red[64][17];

    const int b   = blockIdx.z;
    const int oc0 = blockIdx.y * 64;
    const int p0  = blockIdx.x * 64;
    const int tid = threadIdx.x;
    const int og  = tid >> 4;
    const int pg  = tid & 15;

    unsigned long long acc2[4][2];
#pragma unroll
    for (int i = 0; i < 4; i++) { acc2[i][0] = 0ull; acc2[i][1] = 0ull; }

    for (int k0 = 0; k0 < C1; k0 += 8) {
        __syncthreads();
        for (int i4 = tid; i4 < 128; i4 += 256) {
            int kc = i4 >> 4, p = (i4 & 15) * 4;
            *(float4*)&xs[kc][p] =
                *(const float4*)&x[(size_t)(b * C1 + k0 + kc) * HW + p0 + p];
        }
        for (int i = tid; i < 512; i += 256) {
            int oc = i >> 3, kc = i & 7;
            ws[kc][oc] = w1[(oc0 + oc) * C1 + k0 + kc];
        }
        __syncthreads();
#pragma unroll
        for (int kc = 0; kc < 8; kc++) {
            ulonglong2 xv = *(const ulonglong2*)&xs[kc][pg * 4];
            float4 wv = *(const float4*)&ws[kc][og * 4];
            unsigned long long wb[4];
            wb[0] = pack2(wv.x, wv.x);
            wb[1] = pack2(wv.y, wv.y);
            wb[2] = pack2(wv.z, wv.z);
            wb[3] = pack2(wv.w, wv.w);
#pragma unroll
            for (int i = 0; i < 4; i++) {
                ffma2(acc2[i][0], wb[i], xv.x);
                ffma2(acc2[i][1], wb[i], xv.y);
            }
        }
    }

    float yv[4][4];
#pragma unroll
    for (int i = 0; i < 4; i++) {
        float a0, a1, a2, a3;
        unpack2(a0, a1, acc2[i][0]);
        unpack2(a2, a3, acc2[i][1]);
        float av[4] = {a0, a1, a2, a3};
        int oc = oc0 + og * 4 + i;
        float sc = bng[oc] * rsqrtf(bnv[oc] + EPSF);
        float bi = bnb[oc] - bnm[oc] * sc;
#pragma unroll
        for (int j = 0; j < 4; j++) {
            float t = av[j] * sc + bi;
            yv[i][j] = t / (1.f + expf(-t));
        }
        float4 st = {yv[i][0], yv[i][1], yv[i][2], yv[i][3]};
        *(float4*)&g_y[(size_t)(b * C2 + oc) * HW + p0 + pg * 4] = st;
    }
#pragma unroll
    for (int i = 0; i < 4; i++)
        red[og * 4 + i][pg] = yv[i][0] + yv[i][1] + yv[i][2] + yv[i][3];
    __syncthreads();
    if (tid < 64) {
        float t = 0.f;
#pragma unroll
        for (int p = 0; p < 16; p++) t += red[tid][p];
        g_partsum[(size_t)(b * C2 + oc0 + tid) * NPXT + blockIdx.x] = t;
    }
    __syncthreads();
#pragma unroll
    for (int i = 0; i < 4; i++)
        red[og * 4 + i][pg] = yv[i][0] * yv[i][0] + yv[i][1] * yv[i][1] +
                              yv[i][2] * yv[i][2] + yv[i][3] * yv[i][3];
    __syncthreads();
    if (tid < 64) {
        float t = 0.f;
#pragma unroll
        for (int p = 0; p < 16; p++) t += red[tid][p];
        g_partsq[(size_t)(b * C2 + oc0 + tid) * NPXT + blockIdx.x] = t;
    }
}

// ============================================================================
// Kernel B1: reduce partials -> mu, inv_std
// ============================================================================
__global__ void k_stats()
{
    int i = blockIdx.x * blockDim.x + threadIdx.x;
    if (i >= BB * C2) return;
    const float* ps = &g_partsum[(size_t)i * NPXT];
    const float* pq = &g_partsq [(size_t)i * NPXT];
    float s = 0.f, q = 0.f;
    for (int j = 0; j < NPXT; j++) { s += ps[j]; q += pq[j]; }
    float mu  = s * (1.f / HW);
    float var = q * (1.f / HW) - mu * mu;
    g_mu[i]  = mu;
    g_inv[i] = rsqrtf(var + EPSF);
}

// ============================================================================
// Kernel B2: attention
// ============================================================================
__global__ void k_attn(
    const float* __restrict__ fc1w, const float* __restrict__ fc1b,
    const float* __restrict__ fc2w, const float* __restrict__ fc2b)
{
    int b = threadIdx.x >> 5;
    int lane = threadIdx.x & 31;
    float p4[KK] = {0.f, 0.f, 0.f, 0.f};
    for (int c = lane; c < C2; c += 32) {
        float pv = g_mu[b * C2 + c];
#pragma unroll
        for (int k = 0; k < KK; k++) p4[k] += pv * fc1w[k * C2 + c];
    }
#pragma unroll
    for (int off = 16; off > 0; off >>= 1)
#pragma unroll
        for (int k = 0; k < KK; k++)
            p4[k] += __shfl_down_sync(0xffffffffu, p4[k], off);
    if (lane == 0) {
        float a[KK];
#pragma unroll
        for (int k = 0; k < KK; k++) a[k] = fmaxf(p4[k] + fc1b[k], 0.f);
        float l[KK];
        float mx = -1e30f;
#pragma unroll
        for (int j = 0; j < KK; j++) {
            float t = fc2b[j];
#pragma unroll
            for (int k = 0; k < KK; k++) t += a[k] * fc2w[j * KK + k];
            l[j] = t;
            mx = fmaxf(mx, t);
        }
        float e[KK], s = 0.f;
#pragma unroll
        for (int j = 0; j < KK; j++) { e[j] = expf(l[j] - mx); s += e[j]; }
        float inv = 1.f / s;
#pragma unroll
        for (int j = 0; j < KK; j++) g_attn[b * KK + j] = e[j] * inv;
    }
}

// ============================================================================
// Kernel C: agg_w[b][ic][tap][oc] (tf32-rounded), agg_b[b][oc]
// ============================================================================
__global__ void __launch_bounds__(256) k_agg(
    const float* __restrict__ dyw, const float* __restrict__ dyb)
{
    __shared__ float s_attn[BB * KK];
    if (threadIdx.x < BB * KK) s_attn[threadIdx.x] = g_attn[threadIdx.x];
    __syncthreads();

    int t  = blockIdx.x * 256 + threadIdx.x;
    int oc = t & 255;
    int ic = t >> 8;

    float d[KK][9];
#pragma unroll
    for (int k = 0; k < KK; k++) {
        const float* p = &dyw[((size_t)(k * C2 + oc) * C2 + ic) * 9];
#pragma unroll
        for (int tap = 0; tap < 9; tap++) d[k][tap] = p[tap];
    }
    for (int b = 0; b < BB; b++) {
        float a0 = s_attn[b * KK + 0], a1 = s_attn[b * KK + 1];
        float a2 = s_attn[b * KK + 2], a3 = s_attn[b * KK + 3];
#pragma unroll
        for (int tap = 0; tap < 9; tap++) {
            float w = a0 * d[0][tap] + a1 * d[1][tap] + a2 * d[2][tap] + a3 * d[3][tap];
            g_aggw[((size_t)(b * C2 + ic) * 9 + tap) * C2 + oc] =
                __uint_as_float(tf32r(w));
        }
    }
    if (ic == 0) {
        for (int b = 0; b < BB; b++) {
            float v = 0.f;
#pragma unroll
            for (int k = 0; k < KK; k++)
                v += s_attn[b * KK + k] * dyb[k * C2 + oc];
            g_aggb[b * C2 + oc] = v;
        }
    }
}

// ============================================================================
// Kernel D: per-sample 3x3 conv as implicit TF32 GEMM with halo reuse.
//
// CTA tile: 128 oc x 256 px (16x16 spatial). 512 threads = 16 warps
// (wm 0..3 -> 32 oc, wn 0..3 -> 64 px). Warp kstep = 2 m-frags x 8 n-frags.
// Per 16-ic chunk: fill 18x18 halo once (IN + tf32 fused, OOB=0); all 9 taps
// read B fragments from the halo via shifted addressing (9x less B traffic,
// 2 barriers per chunk). A fragments are loaded directly from g_aggw (L1-hot).
// Halo ic-stride 328 (== 8 mod 32) -> conflict-free fragment LDS.
// ============================================================================
#define CH   16     // ic per chunk
#define NCH  (C2 / CH)
#define HSTR 328    // halo ic stride in words (324 padded)

__global__ void __launch_bounds__(512) k_dyconv(
    const float* __restrict__ b1g, const float* __restrict__ b1b,
    const float* __restrict__ b1m, const float* __restrict__ b1v,
    float* __restrict__ out)
{
    __shared__ uint32_t hs[CH][HSTR];    // halo tile, tf32 bits (~21 KB)
    __shared__ float s_mu[C2], s_inv[C2];

    const int tid = threadIdx.x;
    const int b   = blockIdx.z;
    const int oc0 = blockIdx.y * 128;
    const int t   = blockIdx.x;            // 0..24
    const int gy0 = (t / 5) * 16;
    const int gx0 = (t % 5) * 16;

    const int warp = tid >> 5;
    const int lane = tid & 31;
    const int wm   = warp >> 2;            // 0..3 (32 oc)
    const int wn   = warp & 3;             // 0..3 (64 px)
    const int lr   = lane >> 2;            // 0..7
    const int lc   = lane & 3;             // 0..3

    if (tid < C2) {
        s_mu[tid]  = g_mu[b * C2 + tid];
        s_inv[tid] = g_inv[b * C2 + tid];
    }

    float acc[2][8][4];
#pragma unroll
    for (int mt = 0; mt < 2; mt++)
#pragma unroll
        for (int nt = 0; nt < 8; nt++)
#pragma unroll
            for (int q = 0; q < 4; q++) acc[mt][nt][q] = 0.f;

    const float* aggw_b = g_aggw + (size_t)b * C2 * 9 * C2 + oc0;
    const float* ybase  = g_y + (size_t)b * C2 * HW;

    for (int ch = 0; ch < NCH; ch++) {
        const int ic0 = ch * CH;
        __syncthreads();   // previous chunk's readers done (also orders s_mu)

        // ---- fill 18x18 halo for 16 ic, IN + tf32 fused, OOB = 0 ----
        for (int idx = tid; idx < CH * 324; idx += 512) {
            const int icc = idx / 324;
            const int rem = idx - icc * 324;
            const int rr  = rem / 18;
            const int cc  = rem - rr * 18;
            const int gy  = gy0 + rr - 1;
            const int gx  = gx0 + cc - 1;
            float v = 0.f;
            const int chn = ic0 + icc;
            if ((unsigned)gy < (unsigned)HH && (unsigned)gx < (unsigned)WW)
                v = (ybase[(size_t)chn * HW + gy * WW + gx] - s_mu[chn]) * s_inv[chn];
            hs[icc][rr * 18 + cc] = tf32r(v);
        }
        __syncthreads();

        // ---- 9 taps, 2 ksteps each ----
#pragma unroll
        for (int tap = 0; tap < 9; tap++) {
            const int dy = tap / 3;       // 0..2 (halo origin already at -1)
            const int dx = tap - dy * 3;  // 0..2
#pragma unroll
            for (int ks = 0; ks < 2; ks++) {
                const int k0 = ks * 8;
                // A fragments: direct from global (L1-hot, 4 warps share)
                const float* a_k  = aggw_b + ((size_t)(ic0 + k0 + lc) * 9 + tap) * C2;
                const float* a_k4 = aggw_b + ((size_t)(ic0 + k0 + lc + 4) * 9 + tap) * C2;
                uint32_t afr[2][4];
#pragma unroll
                for (int mt = 0; mt < 2; mt++) {
                    const int oc = wm * 32 + mt * 16 + lr;
                    afr[mt][0] = __float_as_uint(a_k [oc]);
                    afr[mt][1] = __float_as_uint(a_k [oc + 8]);
                    afr[mt][2] = __float_as_uint(a_k4[oc]);
                    afr[mt][3] = __float_as_uint(a_k4[oc + 8]);
                }
                // B fragments from halo, shifted by (dy, dx)
                uint32_t bfr[8][2];
#pragma unroll
                for (int nt = 0; nt < 8; nt++) {
                    const int r = wn * 4 + (nt >> 1);
                    const int c = (nt & 1) * 8 + lr;
                    const int off = (r + dy) * 18 + (c + dx);
                    bfr[nt][0] = hs[k0 + lc    ][off];
                    bfr[nt][1] = hs[k0 + lc + 4][off];
                }
#pragma unroll
                for (int mt = 0; mt < 2; mt++)
#pragma unroll
                    for (int nt = 0; nt < 8; nt++)
                        asm volatile(
                            "mma.sync.aligned.m16n8k8.row.col.f32.tf32.tf32.f32 "
                            "{%0,%1,%2,%3}, {%4,%5,%6,%7}, {%8,%9}, {%0,%1,%2,%3};"
                            : "+f"(acc[mt][nt][0]), "+f"(acc[mt][nt][1]),
                              "+f"(acc[mt][nt][2]), "+f"(acc[mt][nt][3])
                            : "r"(afr[mt][0]), "r"(afr[mt][1]),
                              "r"(afr[mt][2]), "r"(afr[mt][3]),
                              "r"(bfr[nt][0]), "r"(bfr[nt][1]));
            }
        }
    }

    // ---- epilogue: + agg_b, bn1 affine, store ----
#pragma unroll
    for (int mt = 0; mt < 2; mt++) {
#pragma unroll
        for (int h = 0; h < 2; h++) {
            const int oc = oc0 + wm * 32 + mt * 16 + lr + h * 8;
            const float sc = b1g[oc] * rsqrtf(b1v[oc] + EPSF);
            const float bi = b1b[oc] - b1m[oc] * sc;
            const float ab = g_aggb[b * C2 + oc];
            float* obase = &out[(size_t)(b * C2 + oc) * HW];
#pragma unroll
            for (int nt = 0; nt < 8; nt++) {
                const int r  = wn * 4 + (nt >> 1);
                const int c  = (nt & 1) * 8 + 2 * lc;
                const int gy = gy0 + r;
                const int gx = gx0 + c;
                float2 o;
                o.x = (acc[mt][nt][h * 2 + 0] + ab) * sc + bi;
                o.y = (acc[mt][nt][h * 2 + 1] + ab) * sc + bi;
                *(float2*)&obase[gy * WW + gx] = o;
            }
        }
    }
}

// ============================================================================
extern "C" void kernel_launch(void* const* d_in, const int* in_sizes, int n_in,
                              void* d_out, int out_size)
{
    (void)in_sizes; (void)n_in; (void)out_size;
    const float* x    = (const float*)d_in[0];
    const float* w1   = (const float*)d_in[1];
    const float* bng  = (const float*)d_in[2];
    const float* bnb  = (const float*)d_in[3];
    const float* bnm  = (const float*)d_in[4];
    const float* bnv  = (const float*)d_in[5];
    const float* fc1w = (const float*)d_in[6];
    const float* fc1b = (const float*)d_in[7];
    const float* fc2w = (const float*)d_in[8];
    const float* fc2b = (const float*)d_in[9];
    const float* dyw  = (const float*)d_in[10];
    const float* dyb  = (const float*)d_in[11];
    const float* b1g  = (const float*)d_in[12];
    const float* b1b  = (const float*)d_in[13];
    const float* b1m  = (const float*)d_in[14];
    const float* b1v  = (const float*)d_in[15];
    float* out = (float*)d_out;

    k_conv1<<<dim3(NPXT, 4, BB), 256>>>(x, w1, bng, bnb, bnm, bnv);
    k_stats<<<(BB * C2 + 255) / 256, 256>>>();
    k_attn<<<1, 512>>>(fc1w, fc1b, fc2w, fc2b);
    k_agg<<<256, 256>>>(dyw, dyb);
    k_dyconv<<<dim3(25, 2, BB), 512>>>(b1g, b1b, b1m, b1v, out);
}

// round 6
// speedup vs baseline: 1.7690x; 1.7690x over previous
#include <cuda_runtime.h>
#include <cuda_fp16.h>
#include <math.h>
#include <stdint.h>

#define BB 16
#define C1 128
#define C2 256
#define KK 4
#define HH 80
#define WW 80
#define HW 6400
#define EPSF 1e-5f
#define NPXT 100   // 6400/64 px tiles in kernel A

// ---------------- packed fp32x2 helpers (kept for k_conv1) ----------------
__device__ __forceinline__ void ffma2(unsigned long long& d,
                                      unsigned long long a,
                                      unsigned long long b) {
    asm("fma.rn.f32x2 %0, %1, %2, %0;" : "+l"(d) : "l"(a), "l"(b));
}
__device__ __forceinline__ unsigned long long pack2(float lo, float hi) {
    unsigned long long r;
    asm("mov.b64 %0, {%1, %2};" : "=l"(r) : "f"(lo), "f"(hi));
    return r;
}
__device__ __forceinline__ void unpack2(float& lo, float& hi, unsigned long long v) {
    asm("mov.b64 {%0, %1}, %2;" : "=f"(lo), "=f"(hi) : "l"(v));
}
// pack two floats into f16x2 (low = a, high = b)
__device__ __forceinline__ uint32_t packh2(float a, float b) {
    __half2 h = __floats2half2_rn(a, b);
    return *reinterpret_cast<uint32_t*>(&h);
}

// ---------------- scratch (static device globals; no allocs) ----------------
__device__ float g_y[BB * C2 * HW];            // post conv1+BN+SiLU feature
__device__ float g_partsum[BB * C2 * NPXT];
__device__ float g_partsq [BB * C2 * NPXT];
__device__ float g_mu [BB * C2];
__device__ float g_inv[BB * C2];
__device__ float g_attn[BB * KK];
__device__ uint32_t g_aggw_h[(size_t)BB * 9 * 128 * C2]; // [b][tap][icpair][oc] half2
__device__ float g_aggb[BB * C2];

// ============================================================================
// Kernel A: y = SiLU(BN(x @ W1)) + per-(b,c) partial sum / sumsq
// ============================================================================
__global__ void __launch_bounds__(256) k_conv1(
    const float* __restrict__ x, const float* __restrict__ w1,
    const float* __restrict__ bng, const float* __restrict__ bnb,
    const float* __restrict__ bnm, const float* __restrict__ bnv)
{
    __shared__ __align__(16) float xs[8][64];
    __shared__ __align__(16) float ws[8][64];
    __shared__ float red[64][17];

    const int b   = blockIdx.z;
    const int oc0 = blockIdx.y * 64;
    const int p0  = blockIdx.x * 64;
    const int tid = threadIdx.x;
    const int og  = tid >> 4;
    const int pg  = tid & 15;

    unsigned long long acc2[4][2];
#pragma unroll
    for (int i = 0; i < 4; i++) { acc2[i][0] = 0ull; acc2[i][1] = 0ull; }

    for (int k0 = 0; k0 < C1; k0 += 8) {
        __syncthreads();
        for (int i4 = tid; i4 < 128; i4 += 256) {
            int kc = i4 >> 4, p = (i4 & 15) * 4;
            *(float4*)&xs[kc][p] =
                *(const float4*)&x[(size_t)(b * C1 + k0 + kc) * HW + p0 + p];
        }
        for (int i = tid; i < 512; i += 256) {
            int oc = i >> 3, kc = i & 7;
            ws[kc][oc] = w1[(oc0 + oc) * C1 + k0 + kc];
        }
        __syncthreads();
#pragma unroll
        for (int kc = 0; kc < 8; kc++) {
            ulonglong2 xv = *(const ulonglong2*)&xs[kc][pg * 4];
            float4 wv = *(const float4*)&ws[kc][og * 4];
            unsigned long long wb[4];
            wb[0] = pack2(wv.x, wv.x);
            wb[1] = pack2(wv.y, wv.y);
            wb[2] = pack2(wv.z, wv.z);
            wb[3] = pack2(wv.w, wv.w);
#pragma unroll
            for (int i = 0; i < 4; i++) {
                ffma2(acc2[i][0], wb[i], xv.x);
                ffma2(acc2[i][1], wb[i], xv.y);
            }
        }
    }

    float yv[4][4];
#pragma unroll
    for (int i = 0; i < 4; i++) {
        float a0, a1, a2, a3;
        unpack2(a0, a1, acc2[i][0]);
        unpack2(a2, a3, acc2[i][1]);
        float av[4] = {a0, a1, a2, a3};
        int oc = oc0 + og * 4 + i;
        float sc = bng[oc] * rsqrtf(bnv[oc] + EPSF);
        float bi = bnb[oc] - bnm[oc] * sc;
#pragma unroll
        for (int j = 0; j < 4; j++) {
            float t = av[j] * sc + bi;
            yv[i][j] = t / (1.f + expf(-t));
        }
        float4 st = {yv[i][0], yv[i][1], yv[i][2], yv[i][3]};
        *(float4*)&g_y[(size_t)(b * C2 + oc) * HW + p0 + pg * 4] = st;
    }
#pragma unroll
    for (int i = 0; i < 4; i++)
        red[og * 4 + i][pg] = yv[i][0] + yv[i][1] + yv[i][2] + yv[i][3];
    __syncthreads();
    if (tid < 64) {
        float t = 0.f;
#pragma unroll
        for (int p = 0; p < 16; p++) t += red[tid][p];
        g_partsum[(size_t)(b * C2 + oc0 + tid) * NPXT + blockIdx.x] = t;
    }
    __syncthreads();
#pragma unroll
    for (int i = 0; i < 4; i++)
        red[og * 4 + i][pg] = yv[i][0] * yv[i][0] + yv[i][1] * yv[i][1] +
                              yv[i][2] * yv[i][2] + yv[i][3] * yv[i][3];
    __syncthreads();
    if (tid < 64) {
        float t = 0.f;
#pragma unroll
        for (int p = 0; p < 16; p++) t += red[tid][p];
        g_partsq[(size_t)(b * C2 + oc0 + tid) * NPXT + blockIdx.x] = t;
    }
}

// ============================================================================
// Kernel B1: reduce partials -> mu, inv_std
// ============================================================================
__global__ void k_stats()
{
    int i = blockIdx.x * blockDim.x + threadIdx.x;
    if (i >= BB * C2) return;
    const float* ps = &g_partsum[(size_t)i * NPXT];
    const float* pq = &g_partsq [(size_t)i * NPXT];
    float s = 0.f, q = 0.f;
    for (int j = 0; j < NPXT; j++) { s += ps[j]; q += pq[j]; }
    float mu  = s * (1.f / HW);
    float var = q * (1.f / HW) - mu * mu;
    g_mu[i]  = mu;
    g_inv[i] = rsqrtf(var + EPSF);
}

// ============================================================================
// Kernel B2: attention
// ============================================================================
__global__ void k_attn(
    const float* __restrict__ fc1w, const float* __restrict__ fc1b,
    const float* __restrict__ fc2w, const float* __restrict__ fc2b)
{
    int b = threadIdx.x >> 5;
    int lane = threadIdx.x & 31;
    float p4[KK] = {0.f, 0.f, 0.f, 0.f};
    for (int c = lane; c < C2; c += 32) {
        float pv = g_mu[b * C2 + c];
#pragma unroll
        for (int k = 0; k < KK; k++) p4[k] += pv * fc1w[k * C2 + c];
    }
#pragma unroll
    for (int off = 16; off > 0; off >>= 1)
#pragma unroll
        for (int k = 0; k < KK; k++)
            p4[k] += __shfl_down_sync(0xffffffffu, p4[k], off);
    if (lane == 0) {
        float a[KK];
#pragma unroll
        for (int k = 0; k < KK; k++) a[k] = fmaxf(p4[k] + fc1b[k], 0.f);
        float l[KK];
        float mx = -1e30f;
#pragma unroll
        for (int j = 0; j < KK; j++) {
            float t = fc2b[j];
#pragma unroll
            for (int k = 0; k < KK; k++) t += a[k] * fc2w[j * KK + k];
            l[j] = t;
            mx = fmaxf(mx, t);
        }
        float e[KK], s = 0.f;
#pragma unroll
        for (int j = 0; j < KK; j++) { e[j] = expf(l[j] - mx); s += e[j]; }
        float inv = 1.f / s;
#pragma unroll
        for (int j = 0; j < KK; j++) g_attn[b * KK + j] = e[j] * inv;
    }
}

// ============================================================================
// Kernel C: agg_w -> half2 layout [b][tap][icpair][oc], agg_b[b][oc]
// half2 low = even ic, high = odd ic (matches mma k-pair packing).
// ============================================================================
__global__ void __launch_bounds__(256) k_agg(
    const float* __restrict__ dyw, const float* __restrict__ dyb)
{
    __shared__ float s_attn[BB * KK];
    if (threadIdx.x < BB * KK) s_attn[threadIdx.x] = g_attn[threadIdx.x];
    __syncthreads();

    int t  = blockIdx.x * 256 + threadIdx.x;
    int oc = t & 255;
    int ic = t >> 8;

    float d[KK][9];
#pragma unroll
    for (int k = 0; k < KK; k++) {
        const float* p = &dyw[((size_t)(k * C2 + oc) * C2 + ic) * 9];
#pragma unroll
        for (int tap = 0; tap < 9; tap++) d[k][tap] = p[tap];
    }
    __half* aggw16 = reinterpret_cast<__half*>(g_aggw_h);
    for (int b = 0; b < BB; b++) {
        float a0 = s_attn[b * KK + 0], a1 = s_attn[b * KK + 1];
        float a2 = s_attn[b * KK + 2], a3 = s_attn[b * KK + 3];
#pragma unroll
        for (int tap = 0; tap < 9; tap++) {
            float w = a0 * d[0][tap] + a1 * d[1][tap] + a2 * d[2][tap] + a3 * d[3][tap];
            size_t idx = ((((size_t)b * 9 + tap) * 128 + (ic >> 1)) * C2 + oc) * 2 + (ic & 1);
            aggw16[idx] = __float2half_rn(w);
        }
    }
    if (ic == 0) {
        for (int b = 0; b < BB; b++) {
            float v = 0.f;
#pragma unroll
            for (int k = 0; k < KK; k++)
                v += s_attn[b * KK + k] * dyb[k * C2 + oc];
            g_aggb[b * C2 + oc] = v;
        }
    }
}

// ============================================================================
// Kernel D: per-sample 3x3 conv as implicit FP16 GEMM (mma.sync m16n8k16,
// fp32 accumulate). Round-4 skeleton: CTA 128 oc x 128 px (8x16 spatial),
// 256 threads = 8 warps (4 M x 2 N). Stage = one tap x 32 ic (16 k-pairs),
// 72 stages, register prefetch. smem holds half2: As2[kpair][oc],
// Bs2[kpair][px]; stride 136 -> conflict-free fragment loads.
// ============================================================================
#define HSTR2 136

__global__ void __launch_bounds__(256) k_dyconv(
    const float* __restrict__ b1g, const float* __restrict__ b1b,
    const float* __restrict__ b1m, const float* __restrict__ b1v,
    float* __restrict__ out)
{
    __shared__ uint32_t As2[16][HSTR2];   // [kpair][oc] half2 (lo=even ic)
    __shared__ uint32_t Bs2[16][HSTR2];   // [kpair][px] half2
    __shared__ float s_mu[C2], s_inv[C2];

    const int tid = threadIdx.x;
    const int b   = blockIdx.z;
    const int oc0 = blockIdx.y * 128;
    const int tyx = blockIdx.x;          // 0..49
    const int gy0 = (tyx / 5) * 8;
    const int gx0 = (tyx % 5) * 16;

    const int warp = tid >> 5;
    const int lane = tid & 31;
    const int wm   = warp >> 1;          // 0..3
    const int wn   = warp & 1;           // 0..1
    const int lr   = lane >> 2;          // 0..7
    const int lc   = lane & 3;           // 0..3

    // stage-fill thread mapping
    const int a_p  = tid >> 4;           // 0..15 (kpair)
    const int a_oc = (tid & 15) * 8;     // 0..120 (half2 units)
    const int b_n0 = (tid & 31) * 4;     // 0..124 (px)
    const int b_pB = tid >> 5;           // 0..7   (kpair base)

    s_mu[tid]  = g_mu[b * C2 + tid];
    s_inv[tid] = g_inv[b * C2 + tid];
    __syncthreads();

    float acc[2][8][4];
#pragma unroll
    for (int mt = 0; mt < 2; mt++)
#pragma unroll
        for (int nt = 0; nt < 8; nt++)
#pragma unroll
            for (int q = 0; q < 4; q++) acc[mt][nt][q] = 0.f;

    uint4 avr[2];
    float bvr[2][2][4];    // [pair slot][ic parity][px]

    // ---- load stage s into registers ----
    auto load_stage = [&](int s) {
        const int tap = s >> 3;
        const int ic0 = (s & 7) * 32;
        const int dy  = tap / 3 - 1;
        const int dx  = tap % 3 - 1;
        // A: 2 x 16B from half2 layout (pure copy)
        const uint32_t* ap =
            &g_aggw_h[(((size_t)b * 9 + tap) * 128 + (ic0 >> 1) + a_p) * C2 + oc0 + a_oc];
        avr[0] = *(const uint4*)(ap);
        avr[1] = *(const uint4*)(ap + 4);
        // B: 2 kpairs x (2 ic) x 4 px, instance-norm fused
        const int sr  = b_n0 >> 4;
        const int scb = b_n0 & 15;
        const int gy  = gy0 + sr + dy;
        const int gxb = gx0 + scb + dx;
        const bool yok = (unsigned)gy < (unsigned)HH;
#pragma unroll
        for (int pp = 0; pp < 2; pp++) {
            const int pair = b_pB + pp * 8;
#pragma unroll
            for (int par = 0; par < 2; par++) {
                const int ic = ic0 + pair * 2 + par;
                const float mu  = s_mu[ic];
                const float inv = s_inv[ic];
                const float* src = &g_y[(size_t)(b * C2 + ic) * HW + gy * WW + gxb];
#pragma unroll
                for (int q = 0; q < 4; q++) {
                    const int gx = gxb + q;
                    float v = 0.f;
                    if (yok && (unsigned)gx < (unsigned)WW)
                        v = (src[q] - mu) * inv;
                    bvr[pp][par][q] = v;
                }
            }
        }
    };

    // ---- store registers into smem (fp16 pack for B) ----
    auto store_stage = [&]() {
        *(uint4*)&As2[a_p][a_oc]     = avr[0];
        *(uint4*)&As2[a_p][a_oc + 4] = avr[1];
#pragma unroll
        for (int pp = 0; pp < 2; pp++) {
            const int pair = b_pB + pp * 8;
#pragma unroll
            for (int q = 0; q < 4; q++)
                Bs2[pair][b_n0 + q] = packh2(bvr[pp][0][q], bvr[pp][1][q]);
        }
    };

    load_stage(0);

    for (int s = 0; s < 72; s++) {
        __syncthreads();
        store_stage();
        __syncthreads();
        if (s < 71) load_stage(s + 1);

        // ---- compute: 2 ksteps x (2 m-tiles x 8 n-tiles) mma m16n8k16 ----
#pragma unroll
        for (int ks = 0; ks < 2; ks++) {
            const int kp0 = ks * 8;
            uint32_t afr[2][4];
#pragma unroll
            for (int mt = 0; mt < 2; mt++) {
                const int oc = wm * 32 + mt * 16 + lr;
                afr[mt][0] = As2[kp0 + lc][oc];
                afr[mt][1] = As2[kp0 + lc][oc + 8];
                afr[mt][2] = As2[kp0 + lc + 4][oc];
                afr[mt][3] = As2[kp0 + lc + 4][oc + 8];
            }
            uint32_t bfr[8][2];
#pragma unroll
            for (int nt = 0; nt < 8; nt++) {
                const int n = wn * 64 + nt * 8 + lr;
                bfr[nt][0] = Bs2[kp0 + lc][n];
                bfr[nt][1] = Bs2[kp0 + lc + 4][n];
            }
#pragma unroll
            for (int mt = 0; mt < 2; mt++)
#pragma unroll
                for (int nt = 0; nt < 8; nt++)
                    asm volatile(
                        "mma.sync.aligned.m16n8k16.row.col.f32.f16.f16.f32 "
                        "{%0,%1,%2,%3}, {%4,%5,%6,%7}, {%8,%9}, {%0,%1,%2,%3};"
                        : "+f"(acc[mt][nt][0]), "+f"(acc[mt][nt][1]),
                          "+f"(acc[mt][nt][2]), "+f"(acc[mt][nt][3])
                        : "r"(afr[mt][0]), "r"(afr[mt][1]),
                          "r"(afr[mt][2]), "r"(afr[mt][3]),
                          "r"(bfr[nt][0]), "r"(bfr[nt][1]));
        }
    }

    // ---- epilogue: + agg_b, bn1 affine, store (float2 per c-pair) ----
#pragma unroll
    for (int mt = 0; mt < 2; mt++) {
#pragma unroll
        for (int h = 0; h < 2; h++) {
            const int oc = oc0 + wm * 32 + mt * 16 + lr + h * 8;
            const float sc = b1g[oc] * rsqrtf(b1v[oc] + EPSF);
            const float bi = b1b[oc] - b1m[oc] * sc;
            const float ab = g_aggb[b * C2 + oc];
            float* obase = &out[(size_t)(b * C2 + oc) * HW];
#pragma unroll
            for (int nt = 0; nt < 8; nt++) {
                const int n0 = wn * 64 + nt * 8 + 2 * lc;
                const int gy = gy0 + (n0 >> 4);
                const int gx = gx0 + (n0 & 15);
                float2 o;
                o.x = (acc[mt][nt][h * 2 + 0] + ab) * sc + bi;
                o.y = (acc[mt][nt][h * 2 + 1] + ab) * sc + bi;
                *(float2*)&obase[gy * WW + gx] = o;
            }
        }
    }
}

// ============================================================================
extern "C" void kernel_launch(void* const* d_in, const int* in_sizes, int n_in,
                              void* d_out, int out_size)
{
    (void)in_sizes; (void)n_in; (void)out_size;
    const float* x    = (const float*)d_in[0];
    const float* w1   = (const float*)d_in[1];
    const float* bng  = (const float*)d_in[2];
    const float* bnb  = (const float*)d_in[3];
    const float* bnm  = (const float*)d_in[4];
    const float* bnv  = (const float*)d_in[5];
    const float* fc1w = (const float*)d_in[6];
    const float* fc1b = (const float*)d_in[7];
    const float* fc2w = (const float*)d_in[8];
    const float* fc2b = (const float*)d_in[9];
    const float* dyw  = (const float*)d_in[10];
    const float* dyb  = (const float*)d_in[11];
    const float* b1g  = (const float*)d_in[12];
    const float* b1b  = (const float*)d_in[13];
    const float* b1m  = (const float*)d_in[14];
    const float* b1v  = (const float*)d_in[15];
    float* out = (float*)d_out;

    k_conv1<<<dim3(NPXT, 4, BB), 256>>>(x, w1, bng, bnb, bnm, bnv);
    k_stats<<<(BB * C2 + 255) / 256, 256>>>();
    k_attn<<<1, 512>>>(fc1w, fc1b, fc2w, fc2b);
    k_agg<<<256, 256>>>(dyw, dyb);
    k_dyconv<<<dim3(50, 2, BB), 256>>>(b1g, b1b, b1m, b1v, out);
}

// round 7
// speedup vs baseline: 2.1712x; 1.2274x over previous
#include <cuda_runtime.h>
#include <cuda_fp16.h>
#include <math.h>
#include <stdint.h>

#define BB 16
#define C1 128
#define C2 256
#define KK 4
#define HH 80
#define WW 80
#define HW 6400
#define EPSF 1e-5f
#define NPXT 100   // 6400/64 px tiles in kernel A

// ---------------- packed fp32x2 helpers (kept for k_conv1) ----------------
__device__ __forceinline__ void ffma2(unsigned long long& d,
                                      unsigned long long a,
                                      unsigned long long b) {
    asm("fma.rn.f32x2 %0, %1, %2, %0;" : "+l"(d) : "l"(a), "l"(b));
}
__device__ __forceinline__ unsigned long long pack2(float lo, float hi) {
    unsigned long long r;
    asm("mov.b64 %0, {%1, %2};" : "=l"(r) : "f"(lo), "f"(hi));
    return r;
}
__device__ __forceinline__ void unpack2(float& lo, float& hi, unsigned long long v) {
    asm("mov.b64 {%0, %1}, %2;" : "=f"(lo), "=f"(hi) : "l"(v));
}
// pack two floats into f16x2 (low = a, high = b)
__device__ __forceinline__ uint32_t packh2(float a, float b) {
    __half2 h = __floats2half2_rn(a, b);
    return *reinterpret_cast<uint32_t*>(&h);
}

// ---------------- scratch (static device globals; no allocs) ----------------
__device__ float g_y[BB * C2 * HW];            // post conv1+BN+SiLU feature (fp32)
__device__ float g_partsum[BB * C2 * NPXT];
__device__ float g_partsq [BB * C2 * NPXT];
__device__ float g_mu [BB * C2];
__device__ float g_inv[BB * C2];
__device__ float g_attn[BB * KK];
__device__ uint32_t g_aggw_h[(size_t)BB * 9 * 128 * C2]; // [b][tap][icpair][oc] half2
__device__ float g_aggb[BB * C2];
__device__ uint32_t g_yh[(size_t)BB * 128 * HW]; // normalized y, half2 (lo=even ic, hi=odd ic)

// ============================================================================
// Kernel A: y = SiLU(BN(x @ W1)) + per-(b,c) partial sum / sumsq
// ============================================================================
__global__ void __launch_bounds__(256) k_conv1(
    const float* __restrict__ x, const float* __restrict__ w1,
    const float* __restrict__ bng, const float* __restrict__ bnb,
    const float* __restrict__ bnm, const float* __restrict__ bnv)
{
    __shared__ __align__(16) float xs[8][64];
    __shared__ __align__(16) float ws[8][64];
    __shared__ float red[64][17];

    const int b   = blockIdx.z;
    const int oc0 = blockIdx.y * 64;
    const int p0  = blockIdx.x * 64;
    const int tid = threadIdx.x;
    const int og  = tid >> 4;
    const int pg  = tid & 15;

    unsigned long long acc2[4][2];
#pragma unroll
    for (int i = 0; i < 4; i++) { acc2[i][0] = 0ull; acc2[i][1] = 0ull; }

    for (int k0 = 0; k0 < C1; k0 += 8) {
        __syncthreads();
        for (int i4 = tid; i4 < 128; i4 += 256) {
            int kc = i4 >> 4, p = (i4 & 15) * 4;
            *(float4*)&xs[kc][p] =
                *(const float4*)&x[(size_t)(b * C1 + k0 + kc) * HW + p0 + p];
        }
        for (int i = tid; i < 512; i += 256) {
            int oc = i >> 3, kc = i & 7;
            ws[kc][oc] = w1[(oc0 + oc) * C1 + k0 + kc];
        }
        __syncthreads();
#pragma unroll
        for (int kc = 0; kc < 8; kc++) {
            ulonglong2 xv = *(const ulonglong2*)&xs[kc][pg * 4];
            float4 wv = *(const float4*)&ws[kc][og * 4];
            unsigned long long wb[4];
            wb[0] = pack2(wv.x, wv.x);
            wb[1] = pack2(wv.y, wv.y);
            wb[2] = pack2(wv.z, wv.z);
            wb[3] = pack2(wv.w, wv.w);
#pragma unroll
            for (int i = 0; i < 4; i++) {
                ffma2(acc2[i][0], wb[i], xv.x);
                ffma2(acc2[i][1], wb[i], xv.y);
            }
        }
    }

    float yv[4][4];
#pragma unroll
    for (int i = 0; i < 4; i++) {
        float a0, a1, a2, a3;
        unpack2(a0, a1, acc2[i][0]);
        unpack2(a2, a3, acc2[i][1]);
        float av[4] = {a0, a1, a2, a3};
        int oc = oc0 + og * 4 + i;
        float sc = bng[oc] * rsqrtf(bnv[oc] + EPSF);
        float bi = bnb[oc] - bnm[oc] * sc;
#pragma unroll
        for (int j = 0; j < 4; j++) {
            float t = av[j] * sc + bi;
            yv[i][j] = t / (1.f + expf(-t));
        }
        float4 st = {yv[i][0], yv[i][1], yv[i][2], yv[i][3]};
        *(float4*)&g_y[(size_t)(b * C2 + oc) * HW + p0 + pg * 4] = st;
    }
#pragma unroll
    for (int i = 0; i < 4; i++)
        red[og * 4 + i][pg] = yv[i][0] + yv[i][1] + yv[i][2] + yv[i][3];
    __syncthreads();
    if (tid < 64) {
        float t = 0.f;
#pragma unroll
        for (int p = 0; p < 16; p++) t += red[tid][p];
        g_partsum[(size_t)(b * C2 + oc0 + tid) * NPXT + blockIdx.x] = t;
    }
    __syncthreads();
#pragma unroll
    for (int i = 0; i < 4; i++)
        red[og * 4 + i][pg] = yv[i][0] * yv[i][0] + yv[i][1] * yv[i][1] +
                              yv[i][2] * yv[i][2] + yv[i][3] * yv[i][3];
    __syncthreads();
    if (tid < 64) {
        float t = 0.f;
#pragma unroll
        for (int p = 0; p < 16; p++) t += red[tid][p];
        g_partsq[(size_t)(b * C2 + oc0 + tid) * NPXT + blockIdx.x] = t;
    }
}

// ============================================================================
// Kernel B1: reduce partials -> mu, inv_std
// ============================================================================
__global__ void k_stats()
{
    int i = blockIdx.x * blockDim.x + threadIdx.x;
    if (i >= BB * C2) return;
    const float* ps = &g_partsum[(size_t)i * NPXT];
    const float* pq = &g_partsq [(size_t)i * NPXT];
    float s = 0.f, q = 0.f;
    for (int j = 0; j < NPXT; j++) { s += ps[j]; q += pq[j]; }
    float mu  = s * (1.f / HW);
    float var = q * (1.f / HW) - mu * mu;
    g_mu[i]  = mu;
    g_inv[i] = rsqrtf(var + EPSF);
}

// ============================================================================
// Kernel B2: attention
// ============================================================================
__global__ void k_attn(
    const float* __restrict__ fc1w, const float* __restrict__ fc1b,
    const float* __restrict__ fc2w, const float* __restrict__ fc2b)
{
    int b = threadIdx.x >> 5;
    int lane = threadIdx.x & 31;
    float p4[KK] = {0.f, 0.f, 0.f, 0.f};
    for (int c = lane; c < C2; c += 32) {
        float pv = g_mu[b * C2 + c];
#pragma unroll
        for (int k = 0; k < KK; k++) p4[k] += pv * fc1w[k * C2 + c];
    }
#pragma unroll
    for (int off = 16; off > 0; off >>= 1)
#pragma unroll
        for (int k = 0; k < KK; k++)
            p4[k] += __shfl_down_sync(0xffffffffu, p4[k], off);
    if (lane == 0) {
        float a[KK];
#pragma unroll
        for (int k = 0; k < KK; k++) a[k] = fmaxf(p4[k] + fc1b[k], 0.f);
        float l[KK];
        float mx = -1e30f;
#pragma unroll
        for (int j = 0; j < KK; j++) {
            float t = fc2b[j];
#pragma unroll
            for (int k = 0; k < KK; k++) t += a[k] * fc2w[j * KK + k];
            l[j] = t;
            mx = fmaxf(mx, t);
        }
        float e[KK], s = 0.f;
#pragma unroll
        for (int j = 0; j < KK; j++) { e[j] = expf(l[j] - mx); s += e[j]; }
        float inv = 1.f / s;
#pragma unroll
        for (int j = 0; j < KK; j++) g_attn[b * KK + j] = e[j] * inv;
    }
}

// ============================================================================
// Kernel B3: normalize y -> interleaved half2 [b][icpair][px]
// lo = even ic, hi = odd ic (matches mma k-pair packing). 4 px per thread.
// ============================================================================
__global__ void __launch_bounds__(256) k_norm()
{
    const int idx = blockIdx.x * 256 + threadIdx.x;   // 16*128*1600
    const int p4  = (idx % 1600) * 4;
    const int icp = (idx / 1600) & 127;
    const int b   = idx / (1600 * 128);

    const int c0 = b * C2 + icp * 2;
    const float mu0 = g_mu[c0],     iv0 = g_inv[c0];
    const float mu1 = g_mu[c0 + 1], iv1 = g_inv[c0 + 1];

    const float* y0 = &g_y[(size_t)c0 * HW + p4];
    float4 a = *(const float4*)y0;
    float4 c = *(const float4*)(y0 + HW);

    uint4 o;
    o.x = packh2((a.x - mu0) * iv0, (c.x - mu1) * iv1);
    o.y = packh2((a.y - mu0) * iv0, (c.y - mu1) * iv1);
    o.z = packh2((a.z - mu0) * iv0, (c.z - mu1) * iv1);
    o.w = packh2((a.w - mu0) * iv0, (c.w - mu1) * iv1);
    *(uint4*)&g_yh[((size_t)(b * 128 + icp)) * HW + p4] = o;
}

// ============================================================================
// Kernel C: agg_w -> half2 layout [b][tap][icpair][oc], agg_b[b][oc]
// ============================================================================
__global__ void __launch_bounds__(256) k_agg(
    const float* __restrict__ dyw, const float* __restrict__ dyb)
{
    __shared__ float s_attn[BB * KK];
    if (threadIdx.x < BB * KK) s_attn[threadIdx.x] = g_attn[threadIdx.x];
    __syncthreads();

    int t  = blockIdx.x * 256 + threadIdx.x;
    int oc = t & 255;
    int ic = t >> 8;

    float d[KK][9];
#pragma unroll
    for (int k = 0; k < KK; k++) {
        const float* p = &dyw[((size_t)(k * C2 + oc) * C2 + ic) * 9];
#pragma unroll
        for (int tap = 0; tap < 9; tap++) d[k][tap] = p[tap];
    }
    __half* aggw16 = reinterpret_cast<__half*>(g_aggw_h);
    for (int b = 0; b < BB; b++) {
        float a0 = s_attn[b * KK + 0], a1 = s_attn[b * KK + 1];
        float a2 = s_attn[b * KK + 2], a3 = s_attn[b * KK + 3];
#pragma unroll
        for (int tap = 0; tap < 9; tap++) {
            float w = a0 * d[0][tap] + a1 * d[1][tap] + a2 * d[2][tap] + a3 * d[3][tap];
            size_t idx = ((((size_t)b * 9 + tap) * 128 + (ic >> 1)) * C2 + oc) * 2 + (ic & 1);
            aggw16[idx] = __float2half_rn(w);
        }
    }
    if (ic == 0) {
        for (int b = 0; b < BB; b++) {
            float v = 0.f;
#pragma unroll
            for (int k = 0; k < KK; k++)
                v += s_attn[b * KK + k] * dyb[k * C2 + oc];
            g_aggb[b * C2 + oc] = v;
        }
    }
}

// ============================================================================
// Kernel D: per-sample 3x3 conv as implicit FP16 GEMM (mma m16n8k16).
// CTA 128 oc x 128 px, 256 threads = 8 warps (4 M x 2 N). Stage = tap x 32 ic
// (16 kpairs), 72 stages. Double-buffered smem -> 1 sync per stage. B fill is
// pure predicated uint32 copies from pre-normalized g_yh (no IN/pack math).
// ============================================================================
#define HSTR2 136

__global__ void __launch_bounds__(256, 2) k_dyconv(
    const float* __restrict__ b1g, const float* __restrict__ b1b,
    const float* __restrict__ b1m, const float* __restrict__ b1v,
    float* __restrict__ out)
{
    __shared__ uint32_t As2[2][16][HSTR2];   // [buf][kpair][oc] half2
    __shared__ uint32_t Bs2[2][16][HSTR2];   // [buf][kpair][px] half2

    const int tid = threadIdx.x;
    const int b   = blockIdx.z;
    const int oc0 = blockIdx.y * 128;
    const int tyx = blockIdx.x;          // 0..49
    const int gy0 = (tyx / 5) * 8;
    const int gx0 = (tyx % 5) * 16;

    const int warp = tid >> 5;
    const int lane = tid & 31;
    const int wm   = warp >> 1;          // 0..3
    const int wn   = warp & 1;           // 0..1
    const int lr   = lane >> 2;          // 0..7
    const int lc   = lane & 3;           // 0..3

    // stage-fill thread mapping
    const int a_p  = tid >> 4;           // 0..15 (kpair)
    const int a_oc = (tid & 15) * 8;     // 0..120 (half2 units)
    const int b_n0 = (tid & 31) * 4;     // 0..124 (px)
    const int b_pB = tid >> 5;           // 0..7   (kpair base)

    float acc[2][8][4];
#pragma unroll
    for (int mt = 0; mt < 2; mt++)
#pragma unroll
        for (int nt = 0; nt < 8; nt++)
#pragma unroll
            for (int q = 0; q < 4; q++) acc[mt][nt][q] = 0.f;

    uint4 avr[2];
    uint32_t bvr[2][4];    // [pair slot][px]

    const uint32_t* yh_b = &g_yh[(size_t)b * 128 * HW];

    // ---- load stage s into registers ----
    auto load_stage = [&](int s) {
        const int tap  = s >> 3;
        const int icp0 = (s & 7) * 16;       // icpair base
        const int dy   = tap / 3 - 1;
        const int dx   = tap % 3 - 1;
        // A: 2 x 16B (pure copy)
        const uint32_t* ap =
            &g_aggw_h[(((size_t)b * 9 + tap) * 128 + icp0 + a_p) * C2 + oc0 + a_oc];
        avr[0] = *(const uint4*)(ap);
        avr[1] = *(const uint4*)(ap + 4);
        // B: 2 kpair slots x 4 px, predicated uint32 copies
        const int sr  = b_n0 >> 4;
        const int scb = b_n0 & 15;
        const int gy  = gy0 + sr + dy;
        const int gxb = gx0 + scb + dx;
        const bool yok = (unsigned)gy < (unsigned)HH;
#pragma unroll
        for (int pp = 0; pp < 2; pp++) {
            const int icp = icp0 + b_pB + pp * 8;
            const uint32_t* src = yh_b + (size_t)icp * HW + gy * WW + gxb;
#pragma unroll
            for (int q = 0; q < 4; q++) {
                const int gx = gxb + q;
                uint32_t v = 0u;
                if (yok && (unsigned)gx < (unsigned)WW) v = src[q];
                bvr[pp][q] = v;
            }
        }
    };

    // ---- store registers into smem buffer ----
    auto store_stage = [&](int buf) {
        *(uint4*)&As2[buf][a_p][a_oc]     = avr[0];
        *(uint4*)&As2[buf][a_p][a_oc + 4] = avr[1];
#pragma unroll
        for (int pp = 0; pp < 2; pp++) {
            const int pair = b_pB + pp * 8;
            uint4 v = make_uint4(bvr[pp][0], bvr[pp][1], bvr[pp][2], bvr[pp][3]);
            *(uint4*)&Bs2[buf][pair][b_n0] = v;
        }
    };

    load_stage(0);
    store_stage(0);

    for (int s = 0; s < 72; s++) {
        if (s < 71) load_stage(s + 1);
        __syncthreads();                 // buf[s&1] visible; prior mma done
        if (s < 71) store_stage((s + 1) & 1);

        const int bf = s & 1;
#pragma unroll
        for (int ks = 0; ks < 2; ks++) {
            const int kp0 = ks * 8;
            uint32_t afr[2][4];
#pragma unroll
            for (int mt = 0; mt < 2; mt++) {
                const int oc = wm * 32 + mt * 16 + lr;
                afr[mt][0] = As2[bf][kp0 + lc][oc];
                afr[mt][1] = As2[bf][kp0 + lc][oc + 8];
                afr[mt][2] = As2[bf][kp0 + lc + 4][oc];
                afr[mt][3] = As2[bf][kp0 + lc + 4][oc + 8];
            }
            uint32_t bfr[8][2];
#pragma unroll
            for (int nt = 0; nt < 8; nt++) {
                const int n = wn * 64 + nt * 8 + lr;
                bfr[nt][0] = Bs2[bf][kp0 + lc][n];
                bfr[nt][1] = Bs2[bf][kp0 + lc + 4][n];
            }
#pragma unroll
            for (int mt = 0; mt < 2; mt++)
#pragma unroll
                for (int nt = 0; nt < 8; nt++)
                    asm volatile(
                        "mma.sync.aligned.m16n8k16.row.col.f32.f16.f16.f32 "
                        "{%0,%1,%2,%3}, {%4,%5,%6,%7}, {%8,%9}, {%0,%1,%2,%3};"
                        : "+f"(acc[mt][nt][0]), "+f"(acc[mt][nt][1]),
                          "+f"(acc[mt][nt][2]), "+f"(acc[mt][nt][3])
                        : "r"(afr[mt][0]), "r"(afr[mt][1]),
                          "r"(afr[mt][2]), "r"(afr[mt][3]),
                          "r"(bfr[nt][0]), "r"(bfr[nt][1]));
        }
    }

    // ---- epilogue: + agg_b, bn1 affine, store (float2 per c-pair) ----
#pragma unroll
    for (int mt = 0; mt < 2; mt++) {
#pragma unroll
        for (int h = 0; h < 2; h++) {
            const int oc = oc0 + wm * 32 + mt * 16 + lr + h * 8;
            const float sc = b1g[oc] * rsqrtf(b1v[oc] + EPSF);
            const float bi = b1b[oc] - b1m[oc] * sc;
            const float ab = g_aggb[b * C2 + oc];
            float* obase = &out[(size_t)(b * C2 + oc) * HW];
#pragma unroll
            for (int nt = 0; nt < 8; nt++) {
                const int n0 = wn * 64 + nt * 8 + 2 * lc;
                const int gy = gy0 + (n0 >> 4);
                const int gx = gx0 + (n0 & 15);
                float2 o;
                o.x = (acc[mt][nt][h * 2 + 0] + ab) * sc + bi;
                o.y = (acc[mt][nt][h * 2 + 1] + ab) * sc + bi;
                *(float2*)&obase[gy * WW + gx] = o;
            }
        }
    }
}

// ============================================================================
extern "C" void kernel_launch(void* const* d_in, const int* in_sizes, int n_in,
                              void* d_out, int out_size)
{
    (void)in_sizes; (void)n_in; (void)out_size;
    const float* x    = (const float*)d_in[0];
    const float* w1   = (const float*)d_in[1];
    const float* bng  = (const float*)d_in[2];
    const float* bnb  = (const float*)d_in[3];
    const float* bnm  = (const float*)d_in[4];
    const float* bnv  = (const float*)d_in[5];
    const float* fc1w = (const float*)d_in[6];
    const float* fc1b = (const float*)d_in[7];
    const float* fc2w = (const float*)d_in[8];
    const float* fc2b = (const float*)d_in[9];
    const float* dyw  = (const float*)d_in[10];
    const float* dyb  = (const float*)d_in[11];
    const float* b1g  = (const float*)d_in[12];
    const float* b1b  = (const float*)d_in[13];
    const float* b1m  = (const float*)d_in[14];
    const float* b1v  = (const float*)d_in[15];
    float* out = (float*)d_out;

    k_conv1<<<dim3(NPXT, 4, BB), 256>>>(x, w1, bng, bnb, bnm, bnv);
    k_stats<<<(BB * C2 + 255) / 256, 256>>>();
    k_attn<<<1, 512>>>(fc1w, fc1b, fc2w, fc2b);
    k_norm<<<12800, 256>>>();
    k_agg<<<256, 256>>>(dyw, dyb);
    k_dyconv<<<dim3(50, 2, BB), 256>>>(b1g, b1b, b1m, b1v, out);
}

// round 9
// speedup vs baseline: 3.2792x; 1.5103x over previous
#include <cuda_runtime.h>
#include <cuda_fp16.h>
#include <math.h>
#include <stdint.h>

#define BB 16
#define C1 128
#define C2 256
#define KK 4
#define HH 80
#define WW 80
#define HW 6400
#define EPSF 1e-5f
#define NPX1 50    // px tiles (128 px each) for conv1 partial sums

// ---------------- helpers ----------------
__device__ __forceinline__ uint32_t packh2(float a, float b) {
    __half2 h = __floats2half2_rn(a, b);
    return *reinterpret_cast<uint32_t*>(&h);
}
__device__ __forceinline__ uint32_t smem_u32(const void* p) {
    uint32_t a;
    asm("{ .reg .u64 t; cvta.to.shared.u64 t, %1; cvt.u32.u64 %0, t; }"
        : "=r"(a) : "l"(p));
    return a;
}
__device__ __forceinline__ void ldsm_x4(uint32_t addr, uint32_t& r0, uint32_t& r1,
                                        uint32_t& r2, uint32_t& r3) {
    asm volatile("ldmatrix.sync.aligned.m8n8.x4.shared.b16 {%0,%1,%2,%3}, [%4];"
                 : "=r"(r0), "=r"(r1), "=r"(r2), "=r"(r3) : "r"(addr));
}
__device__ __forceinline__ void ldsm_x4_t(uint32_t addr, uint32_t& r0, uint32_t& r1,
                                          uint32_t& r2, uint32_t& r3) {
    asm volatile("ldmatrix.sync.aligned.m8n8.x4.trans.shared.b16 {%0,%1,%2,%3}, [%4];"
                 : "=r"(r0), "=r"(r1), "=r"(r2), "=r"(r3) : "r"(addr));
}
#define MMA16816(acc, a, b)                                                    \
    asm volatile(                                                              \
        "mma.sync.aligned.m16n8k16.row.col.f32.f16.f16.f32 "                   \
        "{%0,%1,%2,%3}, {%4,%5,%6,%7}, {%8,%9}, {%0,%1,%2,%3};"                \
        : "+f"(acc[0]), "+f"(acc[1]), "+f"(acc[2]), "+f"(acc[3])               \
        : "r"(a[0]), "r"(a[1]), "r"(a[2]), "r"(a[3]), "r"(b[0]), "r"(b[1]))

// ---------------- scratch ----------------
__device__ float g_y[BB * C2 * HW];
__device__ float g_partsum[BB * C2 * NPX1];
__device__ float g_partsq [BB * C2 * NPX1];
__device__ float g_mu [BB * C2];
__device__ float g_inv[BB * C2];
__device__ float g_attn[BB * KK];
__device__ __half g_w1h[C2 * C1];                      // [oc][ic]
__device__ __half g_aggw16[(size_t)BB * 9 * C2 * C2];  // [b][tap][oc][ic]
__device__ float g_aggb[BB * C2];
__device__ uint32_t g_yh[(size_t)BB * HW * 128];       // [b][px][icpair] half2

// ============================================================================
// Kernel 0: convert w1 to fp16
// ============================================================================
__global__ void k_w1cvt(const float* __restrict__ w1)
{
    int i = blockIdx.x * 256 + threadIdx.x;
    if (i < C2 * C1) g_w1h[i] = __float2half_rn(w1[i]);
}

// ============================================================================
// Kernel A: conv1 as fp16 implicit GEMM (mma m16n8k16, fp32 accum).
// CTA 128 oc x 128 px, 256 thr = 8 warps (wm 0..3, wn 0..1). K=128, 4 stages
// of K=32, double-buffered. A: g_w1h [oc][k] pitch 80B, ldmatrix non-trans.
// B: x f32 -> f16 in-fill, stored [k][px] pitch 272B, ldmatrix .trans.
// Epilogue: BN + SiLU (fp32), y store, per-(b,oc) partial sum/sumsq.
// ============================================================================
#define A1_PITCH 80
#define A1_SZ    (128 * A1_PITCH)     // 10240
#define B1_PITCH 272
#define B1_SZ    (32 * B1_PITCH)      // 8704

__global__ void __launch_bounds__(256, 2) k_conv1(
    const float* __restrict__ x,
    const float* __restrict__ bng, const float* __restrict__ bnb,
    const float* __restrict__ bnm, const float* __restrict__ bnv)
{
    __shared__ __align__(16) uint8_t sA[2][A1_SZ];
    __shared__ __align__(16) uint8_t sB[2][B1_SZ];
    __shared__ float redS[2][128], redQ[2][128];

    const int tid = threadIdx.x;
    const int b   = blockIdx.z;
    const int oc0 = blockIdx.y * 128;
    const int p0  = blockIdx.x * 128;

    const int warp = tid >> 5;
    const int lane = tid & 31;
    const int wm   = warp >> 1;
    const int wn   = warp & 1;
    const int lr   = lane >> 2;
    const int lc   = lane & 3;

    const uint32_t sAu = smem_u32(sA);
    const uint32_t sBu = smem_u32(sB);
    const uint32_t lbase = (lane & 15);
    const uint32_t lcol  = (lane >> 4) * 16;
    const uint32_t aAddr0 = sAu + (wm * 32 + lbase) * A1_PITCH + lcol;
    const uint32_t bAddr0 = sBu + lbase * B1_PITCH + lcol + (wn * 64) * 2;

    // fill mappings
    const int a_row = tid >> 1;               // 0..127
    const int a_j0  = (tid & 1) * 2;          // uint4 pair
    const int b_kr  = warp * 4;               // 4 k-rows per warp

    const uint4* w1u = (const uint4*)g_w1h;   // row = 16 uint4 (128 ic)
    const float* xb  = x + (size_t)b * C1 * HW + p0;

    float acc[2][8][4];
#pragma unroll
    for (int mt = 0; mt < 2; mt++)
#pragma unroll
        for (int nt = 0; nt < 8; nt++)
#pragma unroll
            for (int q = 0; q < 4; q++) acc[mt][nt][q] = 0.f;

    uint4 aR[2];
    uint32_t bR[4][2];   // 4 k-rows x (2 half2 = 8 px)... per row: 32 lanes x 4px

    auto load_st = [&](int s, int buf) {
        // A: rows = oc, 2 uint4 per thread
#pragma unroll
        for (int i = 0; i < 2; i++)
            aR[i] = w1u[(oc0 + a_row) * 16 + s * 4 + a_j0 + i];
#pragma unroll
        for (int i = 0; i < 2; i++)
            *(uint4*)(sA[buf] + a_row * A1_PITCH + (a_j0 + i) * 16) = aR[i];
        // B: 4 k-rows, lane covers 4 px
#pragma unroll
        for (int i = 0; i < 4; i++) {
            const int kr = b_kr + i;
            float4 v = *(const float4*)(xb + (size_t)(s * 32 + kr) * HW + lane * 4);
            bR[i][0] = packh2(v.x, v.y);
            bR[i][1] = packh2(v.z, v.w);
        }
#pragma unroll
        for (int i = 0; i < 4; i++)
            *(uint2*)(sB[buf] + (b_kr + i) * B1_PITCH + lane * 8) =
                make_uint2(bR[i][0], bR[i][1]);
    };

    load_st(0, 0);

    for (int s = 0; s < 4; s++) {
        __syncthreads();
        if (s < 3) load_st(s + 1, (s + 1) & 1);
        const int buf = s & 1;
#pragma unroll
        for (int ks = 0; ks < 2; ks++) {
            uint32_t afr[2][4];
#pragma unroll
            for (int mt = 0; mt < 2; mt++)
                ldsm_x4(aAddr0 + buf * A1_SZ + mt * (16 * A1_PITCH) + ks * 32,
                        afr[mt][0], afr[mt][1], afr[mt][2], afr[mt][3]);
            uint32_t bfr[8][2];
#pragma unroll
            for (int ng = 0; ng < 4; ng++) {
                uint32_t t0, t1, t2, t3;
                ldsm_x4_t(bAddr0 + buf * B1_SZ + ks * (16 * B1_PITCH) + ng * 32,
                          t0, t1, t2, t3);
                bfr[2 * ng][0] = t0; bfr[2 * ng][1] = t1;
                bfr[2 * ng + 1][0] = t2; bfr[2 * ng + 1][1] = t3;
            }
#pragma unroll
            for (int mt = 0; mt < 2; mt++)
#pragma unroll
                for (int nt = 0; nt < 8; nt++)
                    MMA16816(acc[mt][nt], afr[mt], bfr[nt]);
        }
    }

    // ---- epilogue: BN + SiLU, store y, partial sums ----
    float s4[4] = {0.f, 0.f, 0.f, 0.f};
    float q4[4] = {0.f, 0.f, 0.f, 0.f};
#pragma unroll
    for (int mt = 0; mt < 2; mt++) {
#pragma unroll
        for (int h = 0; h < 2; h++) {
            const int u  = mt * 2 + h;
            const int oc = oc0 + wm * 32 + mt * 16 + h * 8 + lr;
            const float sc = bng[oc] * rsqrtf(bnv[oc] + EPSF);
            const float bi = bnb[oc] - bnm[oc] * sc;
            float* ybase = &g_y[(size_t)(b * C2 + oc) * HW + p0];
#pragma unroll
            for (int nt = 0; nt < 8; nt++) {
                const int px = wn * 64 + nt * 8 + 2 * lc;
                float t0 = acc[mt][nt][h * 2 + 0] * sc + bi;
                float t1 = acc[mt][nt][h * 2 + 1] * sc + bi;
                float y0 = t0 / (1.f + expf(-t0));
                float y1 = t1 / (1.f + expf(-t1));
                s4[u] += y0 + y1;
                q4[u] += y0 * y0 + y1 * y1;
                *(float2*)&ybase[px] = make_float2(y0, y1);
            }
        }
    }
#pragma unroll
    for (int u = 0; u < 4; u++) {
        s4[u] += __shfl_xor_sync(0xffffffffu, s4[u], 1);
        s4[u] += __shfl_xor_sync(0xffffffffu, s4[u], 2);
        q4[u] += __shfl_xor_sync(0xffffffffu, q4[u], 1);
        q4[u] += __shfl_xor_sync(0xffffffffu, q4[u], 2);
    }
    __syncthreads();   // done reading smem tiles (redS/redQ distinct, but order anyway)
    if (lc == 0) {
#pragma unroll
        for (int u = 0; u < 4; u++) {
            const int ocl = wm * 32 + (u >> 1) * 16 + (u & 1) * 8 + lr;
            redS[wn][ocl] = s4[u];
            redQ[wn][ocl] = q4[u];
        }
    }
    __syncthreads();
    if (tid < 128) {
        const size_t o = (size_t)(b * C2 + oc0 + tid) * NPX1 + blockIdx.x;
        g_partsum[o] = redS[0][tid] + redS[1][tid];
        g_partsq [o] = redQ[0][tid] + redQ[1][tid];
    }
}

// ============================================================================
// Kernel B1: stats
// ============================================================================
__global__ void k_stats()
{
    int i = blockIdx.x * blockDim.x + threadIdx.x;
    if (i >= BB * C2) return;
    const float* ps = &g_partsum[(size_t)i * NPX1];
    const float* pq = &g_partsq [(size_t)i * NPX1];
    float s = 0.f, q = 0.f;
    for (int j = 0; j < NPX1; j++) { s += ps[j]; q += pq[j]; }
    float mu  = s * (1.f / HW);
    float var = q * (1.f / HW) - mu * mu;
    g_mu[i]  = mu;
    g_inv[i] = rsqrtf(var + EPSF);
}

// ============================================================================
// Kernel B2: attention
// ============================================================================
__global__ void k_attn(
    const float* __restrict__ fc1w, const float* __restrict__ fc1b,
    const float* __restrict__ fc2w, const float* __restrict__ fc2b)
{
    int b = threadIdx.x >> 5;
    int lane = threadIdx.x & 31;
    float p4[KK] = {0.f, 0.f, 0.f, 0.f};
    for (int c = lane; c < C2; c += 32) {
        float pv = g_mu[b * C2 + c];
#pragma unroll
        for (int k = 0; k < KK; k++) p4[k] += pv * fc1w[k * C2 + c];
    }
#pragma unroll
    for (int off = 16; off > 0; off >>= 1)
#pragma unroll
        for (int k = 0; k < KK; k++)
            p4[k] += __shfl_down_sync(0xffffffffu, p4[k], off);
    if (lane == 0) {
        float a[KK];
#pragma unroll
        for (int k = 0; k < KK; k++) a[k] = fmaxf(p4[k] + fc1b[k], 0.f);
        float l[KK];
        float mx = -1e30f;
#pragma unroll
        for (int j = 0; j < KK; j++) {
            float t = fc2b[j];
#pragma unroll
            for (int k = 0; k < KK; k++) t += a[k] * fc2w[j * KK + k];
            l[j] = t;
            mx = fmaxf(mx, t);
        }
        float e[KK], s = 0.f;
#pragma unroll
        for (int j = 0; j < KK; j++) { e[j] = expf(l[j] - mx); s += e[j]; }
        float inv = 1.f / s;
#pragma unroll
        for (int j = 0; j < KK; j++) g_attn[b * KK + j] = e[j] * inv;
    }
}

// ============================================================================
// Kernel B3: normalize + transpose y -> [b][px][ic] fp16
// ============================================================================
__global__ void __launch_bounds__(256) k_norm()
{
    __shared__ float sm[32][257];
    __shared__ float s_mu[C2], s_inv[C2];

    const int px0 = blockIdx.x * 32;
    const int b   = blockIdx.y;
    const int tid = threadIdx.x;
    const int wid = tid >> 5;
    const int lane = tid & 31;

    if (tid < C2) {
        s_mu[tid]  = g_mu[b * C2 + tid];
        s_inv[tid] = g_inv[b * C2 + tid];
    }
    for (int c = wid; c < C2; c += 8)
        sm[lane][c] = g_y[(size_t)(b * C2 + c) * HW + px0 + lane];
    __syncthreads();

    const int px  = tid & 31;
    const int icg = tid >> 5;
    uint32_t o[16];
#pragma unroll
    for (int j = 0; j < 16; j++) {
        int ic = icg * 32 + 2 * j;
        float a = (sm[px][ic]     - s_mu[ic])     * s_inv[ic];
        float c = (sm[px][ic + 1] - s_mu[ic + 1]) * s_inv[ic + 1];
        o[j] = packh2(a, c);
    }
    uint4* dst = (uint4*)&g_yh[((size_t)(b * HW + px0 + px)) * 128 + icg * 16];
    dst[0] = make_uint4(o[0], o[1], o[2], o[3]);
    dst[1] = make_uint4(o[4], o[5], o[6], o[7]);
    dst[2] = make_uint4(o[8], o[9], o[10], o[11]);
    dst[3] = make_uint4(o[12], o[13], o[14], o[15]);
}

// ============================================================================
// Kernel C: agg weights -> fp16 [b][tap][oc][ic]
// ============================================================================
__global__ void __launch_bounds__(256) k_agg(
    const float* __restrict__ dyw, const float* __restrict__ dyb)
{
    __shared__ float s_attn[BB * KK];
    if (threadIdx.x < BB * KK) s_attn[threadIdx.x] = g_attn[threadIdx.x];
    __syncthreads();

    const int oc = blockIdx.x;
    const int ic = threadIdx.x;

    float d[KK][9];
#pragma unroll
    for (int k = 0; k < KK; k++) {
        const float* p = &dyw[((size_t)(k * C2 + oc) * C2 + ic) * 9];
#pragma unroll
        for (int tap = 0; tap < 9; tap++) d[k][tap] = p[tap];
    }
    for (int b = 0; b < BB; b++) {
        float a0 = s_attn[b * KK + 0], a1 = s_attn[b * KK + 1];
        float a2 = s_attn[b * KK + 2], a3 = s_attn[b * KK + 3];
#pragma unroll
        for (int tap = 0; tap < 9; tap++) {
            float w = a0 * d[0][tap] + a1 * d[1][tap] + a2 * d[2][tap] + a3 * d[3][tap];
            g_aggw16[(((size_t)b * 9 + tap) * C2 + oc) * C2 + ic] = __float2half_rn(w);
        }
    }
    if (ic == 0) {
        for (int b = 0; b < BB; b++) {
            float v = 0.f;
#pragma unroll
            for (int k = 0; k < KK; k++)
                v += s_attn[b * KK + k] * dyb[k * C2 + oc];
            g_aggb[b * C2 + oc] = v;
        }
    }
}

// ============================================================================
// Kernel D: dyconv as fp16 implicit GEMM with ldmatrix fragments.
// CTA 128 oc x 128 px, 256 thr = 8 warps. 72 stages (9 taps x 32 ic),
// double-buffered, 1 sync/stage. A smem [oc][k32] pitch 80B (non-trans LDSM),
// B smem [px][k32] pitch 80B (non-trans LDSM). Sources: g_aggw16 [tap][oc][ic]
// and g_yh [px][ic] (both k-contiguous -> pure uint4 copies, B predicated).
// ============================================================================
#define D_PITCH 80
#define D_SZ    (128 * D_PITCH)       // 10240

__global__ void __launch_bounds__(256, 2) k_dyconv(
    const float* __restrict__ b1g, const float* __restrict__ b1b,
    const float* __restrict__ b1m, const float* __restrict__ b1v,
    float* __restrict__ out)
{
    __shared__ __align__(16) uint8_t sA[2][D_SZ];
    __shared__ __align__(16) uint8_t sB[2][D_SZ];

    const int tid = threadIdx.x;
    const int b   = blockIdx.z;
    const int oc0 = blockIdx.y * 128;
    const int tyx = blockIdx.x;          // 0..49
    const int gy0 = (tyx / 5) * 8;
    const int gx0 = (tyx % 5) * 16;

    const int warp = tid >> 5;
    const int lane = tid & 31;
    const int wm   = warp >> 1;
    const int wn   = warp & 1;
    const int lr   = lane >> 2;
    const int lc   = lane & 3;

    const uint32_t sAu = smem_u32(sA);
    const uint32_t sBu = smem_u32(sB);
    const uint32_t lrow = (lane & 15);
    const uint32_t lcol = (lane >> 4) * 16;
    const uint32_t aAddr0 = sAu + (wm * 32 + lrow) * D_PITCH + lcol;
    const uint32_t bAddr0 = sBu + (wn * 64 + lrow) * D_PITCH + lcol;

    // fill mapping: rows r and r+64, j = uint4 slot
    const int f_r = tid >> 2;            // 0..63
    const int f_j = tid & 3;

    const uint4* aggB = (const uint4*)(g_aggw16 + (size_t)b * 9 * C2 * C2);
    const uint4* yh4  = (const uint4*)(g_yh + (size_t)b * HW * 128);

    float acc[2][8][4];
#pragma unroll
    for (int mt = 0; mt < 2; mt++)
#pragma unroll
        for (int nt = 0; nt < 8; nt++)
#pragma unroll
            for (int q = 0; q < 4; q++) acc[mt][nt][q] = 0.f;

    uint4 aR[2], bR[2];

    auto load_regs = [&](int s) {
        const int tap = s >> 3;
        const int icq = s & 7;
        const int dy  = tap / 3 - 1;
        const int dx  = tap % 3 - 1;
#pragma unroll
        for (int i = 0; i < 2; i++) {
            const int row = i * 64 + f_r;
            aR[i] = aggB[((size_t)tap * C2 + oc0 + row) * 32 + icq * 4 + f_j];
            const int gy = gy0 + (row >> 4) + dy;
            const int gx = gx0 + (row & 15) + dx;
            uint4 v = make_uint4(0u, 0u, 0u, 0u);
            if ((unsigned)gy < (unsigned)HH && (unsigned)gx < (unsigned)WW)
                v = yh4[(size_t)(gy * WW + gx) * 32 + icq * 4 + f_j];
            bR[i] = v;
        }
    };
    auto store_regs = [&](int buf) {
#pragma unroll
        for (int i = 0; i < 2; i++) {
            const int row = i * 64 + f_r;
            *(uint4*)(sA[buf] + row * D_PITCH + f_j * 16) = aR[i];
            *(uint4*)(sB[buf] + row * D_PITCH + f_j * 16) = bR[i];
        }
    };

    load_regs(0);
    store_regs(0);

    for (int s = 0; s < 72; s++) {
        __syncthreads();
        if (s < 71) load_regs(s + 1);
        const int buf = s & 1;
#pragma unroll
        for (int ks = 0; ks < 2; ks++) {
            uint32_t afr[2][4];
#pragma unroll
            for (int mt = 0; mt < 2; mt++)
                ldsm_x4(aAddr0 + buf * D_SZ + mt * (16 * D_PITCH) + ks * 32,
                        afr[mt][0], afr[mt][1], afr[mt][2], afr[mt][3]);
            uint32_t bfr[8][2];
#pragma unroll
            for (int ng = 0; ng < 4; ng++) {
                uint32_t t0, t1, t2, t3;
                ldsm_x4(bAddr0 + buf * D_SZ + ng * (16 * D_PITCH) + ks * 32,
                        t0, t1, t2, t3);
                bfr[2 * ng][0] = t0; bfr[2 * ng][1] = t2;
                bfr[2 * ng + 1][0] = t1; bfr[2 * ng + 1][1] = t3;
            }
#pragma unroll
            for (int mt = 0; mt < 2; mt++)
#pragma unroll
                for (int nt = 0; nt < 8; nt++)
                    MMA16816(acc[mt][nt], afr[mt], bfr[nt]);
        }
        if (s < 71) store_regs((s + 1) & 1);
    }

    // ---- epilogue: + agg_b, bn1 affine, store ----
#pragma unroll
    for (int mt = 0; mt < 2; mt++) {
#pragma unroll
        for (int h = 0; h < 2; h++) {
            const int oc = oc0 + wm * 32 + mt * 16 + lr + h * 8;
            const float sc = b1g[oc] * rsqrtf(b1v[oc] + EPSF);
            const float bi = b1b[oc] - b1m[oc] * sc;
            const float ab = g_aggb[b * C2 + oc];
            float* obase = &out[(size_t)(b * C2 + oc) * HW];
#pragma unroll
            for (int nt = 0; nt < 8; nt++) {
                const int n0 = wn * 64 + nt * 8 + 2 * lc;
                const int gy = gy0 + (n0 >> 4);
                const int gx = gx0 + (n0 & 15);
                float2 o;
                o.x = (acc[mt][nt][h * 2 + 0] + ab) * sc + bi;
                o.y = (acc[mt][nt][h * 2 + 1] + ab) * sc + bi;
                *(float2*)&obase[gy * WW + gx] = o;
            }
        }
    }
}

// ============================================================================
extern "C" void kernel_launch(void* const* d_in, const int* in_sizes, int n_in,
                              void* d_out, int out_size)
{
    (void)in_sizes; (void)n_in; (void)out_size;
    const float* x    = (const float*)d_in[0];
    const float* w1   = (const float*)d_in[1];
    const float* bng  = (const float*)d_in[2];
    const float* bnb  = (const float*)d_in[3];
    const float* bnm  = (const float*)d_in[4];
    const float* bnv  = (const float*)d_in[5];
    const float* fc1w = (const float*)d_in[6];
    const float* fc1b = (const float*)d_in[7];
    const float* fc2w = (const float*)d_in[8];
    const float* fc2b = (const float*)d_in[9];
    const float* dyw  = (const float*)d_in[10];
    const float* dyb  = (const float*)d_in[11];
    const float* b1g  = (const float*)d_in[12];
    const float* b1b  = (const float*)d_in[13];
    const float* b1m  = (const float*)d_in[14];
    const float* b1v  = (const float*)d_in[15];
    float* out = (float*)d_out;

    k_w1cvt<<<128, 256>>>(w1);
    k_conv1<<<dim3(NPX1, 2, BB), 256>>>(x, bng, bnb, bnm, bnv);
    k_stats<<<(BB * C2 + 255) / 256, 256>>>();
    k_attn<<<1, 512>>>(fc1w, fc1b, fc2w, fc2b);
    k_norm<<<dim3(200, BB), 256>>>();
    k_agg<<<256, 256>>>(dyw, dyb);
    k_dyconv<<<dim3(50, 2, BB), 256>>>(b1g, b1b, b1m, b1v, out);
}